// round 13
// baseline (speedup 1.0000x reference)
#include <cuda_runtime.h>
#include <cuda_bf16.h>
#include <math.h>

#define MAXN 50000
#define MAXE 400000

// ---------------- scratch (device globals) ----------------
__device__ float g_hn[MAXN * 128];
__device__ float g_P1[MAXN * 128];
__device__ float g_P2[MAXN * 128];
__device__ float g_Q1[MAXN * 128];
__device__ float g_Q2[MAXN * 128];
__device__ float g_ow[(size_t)MAXE * 32];
__device__ float g_aw[MAXE];
__device__ float g_logits[MAXE];
__device__ float g_Acat[(size_t)MAXN * 288];
__device__ int   g_rowstart[MAXN + 1];
__device__ float g_C1[32 * 128];
__device__ float g_C2[32 * 128];
__device__ float g_C3[32 * 128];
__device__ float g_cvec[128];

// ---------------- helpers ----------------
__device__ __forceinline__ unsigned long long pk2(float x, float y) {
    unsigned long long r;
    asm("mov.b64 %0, {%1, %2};" : "=l"(r) : "f"(x), "f"(y));
    return r;
}
__device__ __forceinline__ unsigned long long ffma2(unsigned long long a,
                                                    unsigned long long b,
                                                    unsigned long long c) {
    unsigned long long d;
    asm("fma.rn.f32x2 %0, %1, %2, %3;" : "=l"(d) : "l"(a), "l"(b), "l"(c));
    return d;
}
__device__ __forceinline__ void upk2(float& lo, float& hi, unsigned long long v) {
    asm("mov.b64 {%0, %1}, %2;" : "=f"(lo), "=f"(hi) : "l"(v));
}
__device__ __forceinline__ void cp16(unsigned int dst_smem, const void* src, bool pred) {
    int sz = pred ? 16 : 0;
    asm volatile("cp.async.ca.shared.global [%0], [%1], 16, %2;"
                 :: "r"(dst_smem), "l"(src), "r"(sz));
}
__device__ __forceinline__ void tf32split(float x, unsigned& hi, unsigned& lo) {
    asm("cvt.rna.tf32.f32 %0, %1;" : "=r"(hi) : "f"(x));
    lo = __float_as_uint(x - __uint_as_float(hi));
}
__device__ __forceinline__ void mma8(float* d, const unsigned* a, unsigned b0, unsigned b1) {
    asm volatile(
        "mma.sync.aligned.m16n8k8.row.col.f32.tf32.tf32.f32 "
        "{%0,%1,%2,%3}, {%4,%5,%6,%7}, {%8,%9}, {%0,%1,%2,%3};"
        : "+f"(d[0]), "+f"(d[1]), "+f"(d[2]), "+f"(d[3])
        : "r"(a[0]), "r"(a[1]), "r"(a[2]), "r"(a[3]), "r"(b0), "r"(b1));
}

// ---------------- K0: segment boundaries (dst sorted) ----------------
__global__ void rowstart_kernel(const int* __restrict__ dst, int E, int Nn) {
    int n = blockIdx.x * blockDim.x + threadIdx.x;
    if (n > Nn) return;
    int lo = 0, hi = E;
    while (lo < hi) {
        int mid = (lo + hi) >> 1;
        if (dst[mid] < n) lo = mid + 1; else hi = mid;
    }
    g_rowstart[n] = lo;
}

// ---------------- prep: combined 32x128 matrices + BN fold ----------------
__global__ void prep_cmat(const float* __restrict__ W3,
                          const float* __restrict__ Wag3,
                          const float* __restrict__ Wee,
                          const float* __restrict__ gamma, const float* __restrict__ beta,
                          const float* __restrict__ mean,  const float* __restrict__ var) {
    int c = threadIdx.x;  // 128
    __shared__ float sWee[1024];
    __shared__ float ssc[32];
    for (int i = c; i < 1024; i += 128) sWee[i] = Wee[i];
    if (c < 32) ssc[c] = gamma[c] * rsqrtf(var[c] + 1e-5f);
    __syncthreads();
    for (int k = 0; k < 32; k++) {
        float a3 = 0.f, a1 = 0.f, a2 = 0.f;
        for (int j = 0; j < 32; j++) {
            float wk = sWee[k * 32 + j];
            a3 = fmaf(wk, W3[j * 128 + c], a3);
            a1 = fmaf(wk, Wag3[j * 128 + c] * ssc[j], a1);
            a2 = fmaf(wk, Wag3[(32 + j) * 128 + c], a2);
        }
        g_C3[k * 128 + c] = a3;
        g_C1[k * 128 + c] = a1;
        g_C2[k * 128 + c] = a2;
    }
    float cv = 0.f;
    for (int j = 0; j < 32; j++)
        cv = fmaf(beta[j] - mean[j] * ssc[j], Wag3[j * 128 + c], cv);
    g_cvec[c] = cv;
}

// ---------------- gemm_v6 (R10): 3xTF32 mma, cp.async double-buffered -------
#define ABUF 4608   // 128*36
#define BBUF 4352   // 32*136
#define BUFSZ (ABUF + BBUF)
__global__ __launch_bounds__(256, 2)
void gemm_v6(const float* __restrict__ A, const float* __restrict__ B,
             const float* __restrict__ bias, float* __restrict__ C,
             int M, int K, int mode) {
    extern __shared__ float sm[];
    int tid = threadIdx.x;
    int lane = tid & 31;
    int wid = tid >> 5;
    int warp_m = wid >> 1;
    int warp_n = wid & 1;
    int g = lane >> 2;
    int t = lane & 3;
    int row0 = blockIdx.x * 128;
    unsigned int smem_base = (unsigned int)__cvta_generic_to_shared(sm);

    float acc[2][8][4];
#pragma unroll
    for (int mi = 0; mi < 2; mi++)
#pragma unroll
        for (int ni = 0; ni < 8; ni++)
#pragma unroll
            for (int q = 0; q < 4; q++) acc[mi][ni][q] = 0.f;

    int nch = K >> 5;

#pragma unroll
    for (int i = 0; i < 4; i++) {
        int idx = tid + 256 * i;
        int r = idx >> 3, kg = idx & 7;
        cp16(smem_base + (r * 36 + kg * 4) * 4,
             &A[(size_t)(row0 + r) * K + kg * 4], row0 + r < M);
    }
#pragma unroll
    for (int i = 0; i < 4; i++) {
        int idx = tid + 256 * i;
        int k = idx >> 5, cg = idx & 31;
        cp16(smem_base + (ABUF + k * 136 + cg * 4) * 4,
             &B[(size_t)k * 128 + cg * 4], true);
    }
    asm volatile("cp.async.commit_group;");

    for (int c = 0; c < nch; c++) {
        int buf = c & 1;
        if (c + 1 < nch) {
            int kc = (c + 1) * 32;
            unsigned int boff = smem_base + ((c + 1) & 1) * BUFSZ * 4;
#pragma unroll
            for (int i = 0; i < 4; i++) {
                int idx = tid + 256 * i;
                int r = idx >> 3, kg = idx & 7;
                cp16(boff + (r * 36 + kg * 4) * 4,
                     &A[(size_t)(row0 + r) * K + kc + kg * 4], row0 + r < M);
            }
#pragma unroll
            for (int i = 0; i < 4; i++) {
                int idx = tid + 256 * i;
                int k = idx >> 5, cg = idx & 31;
                cp16(boff + (ABUF + k * 136 + cg * 4) * 4,
                     &B[(size_t)(kc + k) * 128 + cg * 4], true);
            }
            asm volatile("cp.async.commit_group;");
            asm volatile("cp.async.wait_group 1;");
        } else {
            asm volatile("cp.async.wait_group 0;");
        }
        __syncthreads();

        const float* As = sm + buf * BUFSZ;
        const float* Bs = sm + buf * BUFSZ + ABUF;

#pragma unroll
        for (int k8 = 0; k8 < 4; k8++) {
            int k = k8 * 8;
            unsigned ahi[2][4], alo[2][4];
#pragma unroll
            for (int mi = 0; mi < 2; mi++) {
                int r0 = warp_m * 32 + mi * 16;
                tf32split(As[(r0 + g) * 36 + k + t],         ahi[mi][0], alo[mi][0]);
                tf32split(As[(r0 + g + 8) * 36 + k + t],     ahi[mi][1], alo[mi][1]);
                tf32split(As[(r0 + g) * 36 + k + t + 4],     ahi[mi][2], alo[mi][2]);
                tf32split(As[(r0 + g + 8) * 36 + k + t + 4], ahi[mi][3], alo[mi][3]);
            }
#pragma unroll
            for (int ni = 0; ni < 8; ni++) {
                int cb = warp_n * 64 + ni * 8 + g;
                float bv0 = Bs[(k + t) * 136 + cb];
                float bv1 = Bs[(k + t + 4) * 136 + cb];
                unsigned bh0, bl0, bh1, bl1;
                tf32split(bv0, bh0, bl0);
                tf32split(bv1, bh1, bl1);
#pragma unroll
                for (int mi = 0; mi < 2; mi++) {
                    mma8(acc[mi][ni], ahi[mi], bh0, bh1);
                    mma8(acc[mi][ni], ahi[mi], bl0, bl1);
                    mma8(acc[mi][ni], alo[mi], bh0, bh1);
                }
            }
        }
        __syncthreads();
    }

    float2 bias2[8];
#pragma unroll
    for (int ni = 0; ni < 8; ni++) {
        int col = warp_n * 64 + ni * 8 + 2 * t;
        bias2[ni] = bias ? *(const float2*)&bias[col] : make_float2(0.f, 0.f);
    }
#pragma unroll
    for (int mi = 0; mi < 2; mi++) {
        int rbase = row0 + warp_m * 32 + mi * 16;
#pragma unroll
        for (int h = 0; h < 2; h++) {
            int row = rbase + g + h * 8;
            if (row < M) {
                bool sub = (mode == 1) && (g_rowstart[row + 1] == g_rowstart[row]);
#pragma unroll
                for (int ni = 0; ni < 8; ni++) {
                    int col = warp_n * 64 + ni * 8 + 2 * t;
                    float2 v;
                    if (sub) {
                        v = *(const float2*)&g_hn[(size_t)row * 128 + col];
                    } else {
                        v.x = acc[mi][ni][h * 2 + 0] + bias2[ni].x;
                        v.y = acc[mi][ni][h * 2 + 1] + bias2[ni].y;
                    }
                    *(float2*)&C[(size_t)row * 128 + col] = v;
                }
            }
        }
    }
}

// ---------------- wout_gemm_v3: tensor-core wout ----------------------------
// wout = w@C2 + aw*(w@C1) + Q1[s]+Q2[d]+cvec.  As=[w | aw*w] 128x68,
// Bs=[C2;C1] 64x136.  Single K=64 slab, 3xTF32 mma.
#define WABUF 8704   // 128*68
#define WBBUF 8704   // 64*136
__global__ __launch_bounds__(256, 2)
void wout_gemm_v3(const float* __restrict__ w, const int* __restrict__ src,
                  const int* __restrict__ dst, float* __restrict__ wout, int E) {
    extern __shared__ float sm[];
    float* As = sm;             // 128 x 68
    float* Bs = sm + WABUF;     // 64 x 136
    __shared__ float saw[128];
    int tid = threadIdx.x;
    int lane = tid & 31;
    int wid = tid >> 5;
    int warp_m = wid >> 1;
    int warp_n = wid & 1;
    int g = lane >> 2;
    int t = lane & 3;
    int row0 = blockIdx.x * 128;

    if (tid < 128) saw[tid] = (row0 + tid < E) ? g_aw[row0 + tid] : 0.f;
    __syncthreads();

    // A: 128 rows x 16 float4 (k<32: w, k>=32: aw*w)
#pragma unroll
    for (int i = 0; i < 8; i++) {
        int idx = tid + 256 * i;        // 0..2047
        int r = idx >> 4, kg = idx & 15;
        float4 v = make_float4(0.f, 0.f, 0.f, 0.f);
        if (row0 + r < E)
            v = *(const float4*)&w[(size_t)(row0 + r) * 32 + (kg & 7) * 4];
        if (kg >= 8) {
            float sc = saw[r];
            v.x *= sc; v.y *= sc; v.z *= sc; v.w *= sc;
        }
        *(float4*)&As[r * 68 + kg * 4] = v;
    }
    // B: rows 0..31 = C2, 32..63 = C1
#pragma unroll
    for (int i = 0; i < 8; i++) {
        int idx = tid + 256 * i;        // 0..2047
        int k = idx >> 5, cg = idx & 31;
        const float* Bsrc = (k < 32) ? (g_C2 + k * 128) : (g_C1 + (k - 32) * 128);
        *(float4*)&Bs[k * 136 + cg * 4] = *(const float4*)&Bsrc[cg * 4];
    }
    __syncthreads();

    float acc[2][8][4];
#pragma unroll
    for (int mi = 0; mi < 2; mi++)
#pragma unroll
        for (int ni = 0; ni < 8; ni++)
#pragma unroll
            for (int q = 0; q < 4; q++) acc[mi][ni][q] = 0.f;

#pragma unroll
    for (int k8 = 0; k8 < 8; k8++) {
        int k = k8 * 8;
        unsigned ahi[2][4], alo[2][4];
#pragma unroll
        for (int mi = 0; mi < 2; mi++) {
            int r0 = warp_m * 32 + mi * 16;
            tf32split(As[(r0 + g) * 68 + k + t],         ahi[mi][0], alo[mi][0]);
            tf32split(As[(r0 + g + 8) * 68 + k + t],     ahi[mi][1], alo[mi][1]);
            tf32split(As[(r0 + g) * 68 + k + t + 4],     ahi[mi][2], alo[mi][2]);
            tf32split(As[(r0 + g + 8) * 68 + k + t + 4], ahi[mi][3], alo[mi][3]);
        }
#pragma unroll
        for (int ni = 0; ni < 8; ni++) {
            int cb = warp_n * 64 + ni * 8 + g;
            float bv0 = Bs[(k + t) * 136 + cb];
            float bv1 = Bs[(k + t + 4) * 136 + cb];
            unsigned bh0, bl0, bh1, bl1;
            tf32split(bv0, bh0, bl0);
            tf32split(bv1, bh1, bl1);
#pragma unroll
            for (int mi = 0; mi < 2; mi++) {
                mma8(acc[mi][ni], ahi[mi], bh0, bh1);
                mma8(acc[mi][ni], ahi[mi], bl0, bl1);
                mma8(acc[mi][ni], alo[mi], bh0, bh1);
            }
        }
    }

    // epilogue: + Q1[src] + Q2[dst] + cvec
    float2 cv2[8];
#pragma unroll
    for (int ni = 0; ni < 8; ni++) {
        int col = warp_n * 64 + ni * 8 + 2 * t;
        cv2[ni] = *(const float2*)&g_cvec[col];
    }
#pragma unroll
    for (int mi = 0; mi < 2; mi++) {
        int rbase = row0 + warp_m * 32 + mi * 16;
#pragma unroll
        for (int h = 0; h < 2; h++) {
            int row = rbase + g + h * 8;
            if (row < E) {
                int s = src[row], d = dst[row];
#pragma unroll
                for (int ni = 0; ni < 8; ni++) {
                    int col = warp_n * 64 + ni * 8 + 2 * t;
                    float2 q1 = *(const float2*)&g_Q1[(size_t)s * 128 + col];
                    float2 q2 = *(const float2*)&g_Q2[(size_t)d * 128 + col];
                    float2 v;
                    v.x = acc[mi][ni][h * 2 + 0] + q1.x + q2.x + cv2[ni].x;
                    v.y = acc[mi][ni][h * 2 + 1] + q1.y + q2.y + cv2[ni].y;
                    *(float2*)&wout[(size_t)row * 128 + col] = v;
                }
            }
        }
    }
}

// ---------------- fuse_gemm_v2: merged k_embed + fuse -----------------------
__global__ __launch_bounds__(256, 2)
void fuse_gemm_v2(const float* __restrict__ w,
                  const int* __restrict__ src, const int* __restrict__ dst,
                  const float* __restrict__ Wee, const float* __restrict__ Wsf,
                  const float* __restrict__ bif, const float* __restrict__ Wattn,
                  float* __restrict__ sat_out, int E) {
    __shared__ float As[32][132];
    __shared__ float Bs[32][132];
    __shared__ float Bse[32][36];
    __shared__ float sWsf[32];
    __shared__ float part[128][17];
    __shared__ float ss[128];
    int tid = threadIdx.x;
    int tx = tid & 15;
    int ty = tid >> 4;
    int row0 = blockIdx.x * 128;

    unsigned long long acc[2][4][2][2];
    unsigned long long oacc[2][4];
#pragma unroll
    for (int a = 0; a < 2; a++)
#pragma unroll
        for (int b = 0; b < 4; b++) {
            oacc[a][b] = 0ull;
#pragma unroll
            for (int c = 0; c < 2; c++)
#pragma unroll
                for (int d = 0; d < 2; d++) acc[a][b][c][d] = 0ull;
        }

#pragma unroll
    for (int i = 0; i < 4; i++) {
        int e = tid + 256 * i;
        int r = e >> 3;
        int kg = e & 7;
        float4 v = make_float4(0.f, 0.f, 0.f, 0.f);
        if (row0 + r < E)
            v = *(const float4*)&w[(size_t)(row0 + r) * 32 + kg * 4];
        As[kg * 4 + 0][r] = v.x;
        As[kg * 4 + 1][r] = v.y;
        As[kg * 4 + 2][r] = v.z;
        As[kg * 4 + 3][r] = v.w;
    }
#pragma unroll
    for (int i = 0; i < 4; i++) {
        int e = tid + 256 * i;
        int k = e >> 5;
        int cg = e & 31;
        *(float4*)&Bs[k][cg * 4] = *(const float4*)&g_C3[k * 128 + cg * 4];
    }
    {
        int k = tid >> 3, c4 = tid & 7;
        *(float4*)&Bse[k][c4 * 4] = *(const float4*)&Wee[k * 32 + c4 * 4];
    }
    if (tid < 32) sWsf[tid] = Wsf[tid];
    __syncthreads();

#pragma unroll
    for (int k = 0; k < 32; k++) {
        float4 af0 = *(const float4*)&As[k][ty * 4];
        float4 af1 = *(const float4*)&As[k][64 + ty * 4];
        ulonglong2 b0 = *(const ulonglong2*)&Bs[k][tx * 4];
        ulonglong2 b1 = *(const ulonglong2*)&Bs[k][64 + tx * 4];
        unsigned long long be = *(const unsigned long long*)&Bse[k][tx * 2];
        float av[2][4] = {{af0.x, af0.y, af0.z, af0.w}, {af1.x, af1.y, af1.z, af1.w}};
#pragma unroll
        for (int mi = 0; mi < 2; mi++)
#pragma unroll
            for (int j = 0; j < 4; j++) {
                unsigned long long ap = pk2(av[mi][j], av[mi][j]);
                acc[mi][j][0][0] = ffma2(ap, b0.x, acc[mi][j][0][0]);
                acc[mi][j][0][1] = ffma2(ap, b0.y, acc[mi][j][0][1]);
                acc[mi][j][1][0] = ffma2(ap, b1.x, acc[mi][j][1][0]);
                acc[mi][j][1][1] = ffma2(ap, b1.y, acc[mi][j][1][1]);
                oacc[mi][j]      = ffma2(ap, be,  oacc[mi][j]);
            }
    }
    __syncthreads();

    float sfl = sWsf[tx * 2], sfh = sWsf[tx * 2 + 1];
    float4 bf0 = *(const float4*)&bif[tx * 4];
    float4 bf1 = *(const float4*)&bif[64 + tx * 4];
    float4 wa0 = *(const float4*)&Wattn[tx * 4];
    float4 wa1 = *(const float4*)&Wattn[64 + tx * 4];

#pragma unroll
    for (int mi = 0; mi < 2; mi++)
#pragma unroll
        for (int j = 0; j < 4; j++) {
            int rl = mi * 64 + ty * 4 + j;
            int row = row0 + rl;
            float olo, ohi;
            upk2(olo, ohi, oacc[mi][j]);
            float llo = olo > 0.f ? olo : 0.1f * olo;
            float lhi = ohi > 0.f ? ohi : 0.1f * ohi;
            float ps = fmaf(llo, sfl, lhi * sfh);
            ps += __shfl_xor_sync(0xffffffffu, ps, 1);
            ps += __shfl_xor_sync(0xffffffffu, ps, 2);
            ps += __shfl_xor_sync(0xffffffffu, ps, 4);
            ps += __shfl_xor_sync(0xffffffffu, ps, 8);
            float sE = ps;
            if (tx == 0) ss[rl] = sE;

            float partial = 0.f;
            if (row < E) {
                float2 owv = make_float2(olo, ohi);
                *(float2*)&g_ow[(size_t)row * 32 + tx * 2] = owv;
                float2 sow = make_float2(sE * olo, sE * ohi);
                *(float2*)&sat_out[(size_t)row * 288 + 256 + tx * 2] = sow;

                int s = src[row], d = dst[row];
                float4 p1a = *(const float4*)&g_P1[(size_t)s * 128 + tx * 4];
                float4 p2a = *(const float4*)&g_P2[(size_t)d * 128 + tx * 4];
                float4 p1b = *(const float4*)&g_P1[(size_t)s * 128 + 64 + tx * 4];
                float4 p2b = *(const float4*)&g_P2[(size_t)d * 128 + 64 + tx * 4];
                float z[8];
                upk2(z[0], z[1], acc[mi][j][0][0]);
                upk2(z[2], z[3], acc[mi][j][0][1]);
                upk2(z[4], z[5], acc[mi][j][1][0]);
                upk2(z[6], z[7], acc[mi][j][1][1]);
                z[0] = fmaf(sE, z[0], p1a.x + p2a.x + bf0.x);
                z[1] = fmaf(sE, z[1], p1a.y + p2a.y + bf0.y);
                z[2] = fmaf(sE, z[2], p1a.z + p2a.z + bf0.z);
                z[3] = fmaf(sE, z[3], p1a.w + p2a.w + bf0.w);
                z[4] = fmaf(sE, z[4], p1b.x + p2b.x + bf1.x);
                z[5] = fmaf(sE, z[5], p1b.y + p2b.y + bf1.y);
                z[6] = fmaf(sE, z[6], p1b.z + p2b.z + bf1.z);
                z[7] = fmaf(sE, z[7], p1b.w + p2b.w + bf1.w);
                float wv[8] = {wa0.x, wa0.y, wa0.z, wa0.w, wa1.x, wa1.y, wa1.z, wa1.w};
#pragma unroll
                for (int c = 0; c < 8; c++) {
                    float l = z[c] > 0.f ? z[c] : 0.1f * z[c];
                    partial = fmaf(l, wv[c], partial);
                }
                size_t so = (size_t)row * 288;
                *(float4*)&sat_out[so + tx * 4]        = *(const float4*)&g_hn[(size_t)s * 128 + tx * 4];
                *(float4*)&sat_out[so + 64 + tx * 4]   = *(const float4*)&g_hn[(size_t)s * 128 + 64 + tx * 4];
                *(float4*)&sat_out[so + 128 + tx * 4]  = *(const float4*)&g_hn[(size_t)d * 128 + tx * 4];
                *(float4*)&sat_out[so + 192 + tx * 4]  = *(const float4*)&g_hn[(size_t)d * 128 + 64 + tx * 4];
            }
            part[rl][tx] = partial;
        }
    __syncthreads();
    if (tid < 128) {
        int row = row0 + tid;
        if (row < E) {
            float v = 0.f;
#pragma unroll
            for (int i = 0; i < 16; i++) v += part[tid][i];
            g_logits[row] = v;
            g_aw[row] = v * ss[tid];
        }
    }
}

// ---------------- segment softmax + aggregate + hn copy (warp per node) -----
__global__ void segment_kernel(const int* __restrict__ src, int Nn) {
    int warp = (blockIdx.x * blockDim.x + threadIdx.x) >> 5;
    int lane = threadIdx.x & 31;
    if (warp >= Nn) return;
    int s0 = g_rowstart[warp], s1 = g_rowstart[warp + 1];
    float acc[5] = {0.f, 0.f, 0.f, 0.f, 0.f};
    if (s1 > s0) {
        float m = -INFINITY;
        for (int e = s0 + lane; e < s1; e += 32) m = fmaxf(m, g_logits[e]);
#pragma unroll
        for (int o = 16; o; o >>= 1) m = fmaxf(m, __shfl_xor_sync(0xffffffffu, m, o));
        float den = 0.f;
        for (int e = s0 + lane; e < s1; e += 32) den += expf(g_logits[e] - m);
#pragma unroll
        for (int o = 16; o; o >>= 1) den += __shfl_xor_sync(0xffffffffu, den, o);
        float inv = 1.0f / den;
        for (int e = s0; e < s1; e++) {
            float alpha = expf(g_logits[e] - m) * inv;
            int sidx = src[e];
#pragma unroll
            for (int i = 0; i < 4; i++)
                acc[i] = fmaf(alpha, g_hn[(size_t)sidx * 128 + lane + 32 * i], acc[i]);
            acc[4] = fmaf(alpha * g_aw[e], g_ow[(size_t)e * 32 + lane], acc[4]);
        }
    }
#pragma unroll
    for (int i = 0; i < 4; i++) g_Acat[(size_t)warp * 288 + lane + 32 * i] = acc[i];
    g_Acat[(size_t)warp * 288 + 128 + lane] = acc[4];
    float4 hv = *(const float4*)&g_hn[(size_t)warp * 128 + lane * 4];
    *(float4*)&g_Acat[(size_t)warp * 288 + 160 + lane * 4] = hv;
}

// ---------------- launch ----------------
extern "C" void kernel_launch(void* const* d_in, const int* in_sizes, int n_in,
                              void* d_out, int out_size) {
    const float* h        = (const float*)d_in[0];
    const float* w        = (const float*)d_in[1];
    const int*   src      = (const int*)d_in[2];
    const int*   dst      = (const int*)d_in[3];
    const float* W_en     = (const float*)d_in[4];
    const float* W_attn   = (const float*)d_in[5];
    const float* W_if     = (const float*)d_in[6];
    const float* b_if     = (const float*)d_in[7];
    const float* W_ee     = (const float*)d_in[8];
    const float* W_sf     = (const float*)d_in[9];
    const float* W_conc   = (const float*)d_in[10];
    const float* b_conc   = (const float*)d_in[11];
    const float* bn_gamma = (const float*)d_in[12];
    const float* bn_beta  = (const float*)d_in[13];
    const float* bn_mean  = (const float*)d_in[14];
    const float* bn_var   = (const float*)d_in[15];
    const float* W_ag     = (const float*)d_in[16];

    int Nn = in_sizes[0] / 128;
    int E  = in_sizes[2];

    float* out_hnew = (float*)d_out;
    float* out_wout = out_hnew + (size_t)Nn * 128;
    float* out_sat  = out_wout + (size_t)E * 128;

    float *hn_p, *P1_p, *P2_p, *Q1_p, *Q2_p, *Acat_p;
    cudaGetSymbolAddress((void**)&hn_p,   g_hn);
    cudaGetSymbolAddress((void**)&P1_p,   g_P1);
    cudaGetSymbolAddress((void**)&P2_p,   g_P2);
    cudaGetSymbolAddress((void**)&Q1_p,   g_Q1);
    cudaGetSymbolAddress((void**)&Q2_p,   g_Q2);
    cudaGetSymbolAddress((void**)&Acat_p, g_Acat);

    const int G6_SMEM = 2 * BUFSZ * 4;          // 71680 bytes
    const int WO_SMEM = (WABUF + WBBUF) * 4;    // 69632 bytes
    cudaFuncSetAttribute(gemm_v6, cudaFuncAttributeMaxDynamicSharedMemorySize, G6_SMEM);
    cudaFuncSetAttribute(wout_gemm_v3, cudaFuncAttributeMaxDynamicSharedMemorySize, WO_SMEM);

    int gbN = (Nn + 127) / 128;
    int gbE = (E + 127) / 128;

    rowstart_kernel<<<(Nn + 256) / 256, 256>>>(dst, E, Nn);
    prep_cmat<<<1, 128>>>(W_if + 256 * 128, W_ag + 256 * 128, W_ee,
                          bn_gamma, bn_beta, bn_mean, bn_var);
    gemm_v6<<<gbN, 256, G6_SMEM>>>(h, W_en, nullptr, hn_p, Nn, 128, 0);
    gemm_v6<<<gbN, 256, G6_SMEM>>>(hn_p, W_if,             nullptr, P1_p, Nn, 128, 0);
    gemm_v6<<<gbN, 256, G6_SMEM>>>(hn_p, W_if + 128 * 128, nullptr, P2_p, Nn, 128, 0);
    fuse_gemm_v2<<<gbE, 256>>>(w, src, dst, W_ee, W_sf, b_if, W_attn, out_sat, E);
    segment_kernel<<<(Nn + 7) / 8, 256>>>(src, Nn);
    gemm_v6<<<gbN, 256, G6_SMEM>>>(Acat_p, W_conc, b_conc, out_hnew, Nn, 288, 1);
    gemm_v6<<<gbN, 256, G6_SMEM>>>(out_hnew, W_ag,             nullptr, Q1_p, Nn, 128, 0);
    gemm_v6<<<gbN, 256, G6_SMEM>>>(out_hnew, W_ag + 128 * 128, nullptr, Q2_p, Nn, 128, 0);
    wout_gemm_v3<<<gbE, 256, WO_SMEM>>>(w, src, dst, out_wout, E);
}

// round 14
// speedup vs baseline: 1.0654x; 1.0654x over previous
#include <cuda_runtime.h>
#include <cuda_bf16.h>
#include <math.h>

#define MAXN 50000
#define MAXE 400000

// ---------------- scratch (device globals) ----------------
__device__ float g_hn[MAXN * 128];
__device__ float g_P1[MAXN * 128];
__device__ float g_P2[MAXN * 128];
__device__ float g_Q1[MAXN * 128];
__device__ float g_Q2[MAXN * 128];
__device__ float g_ow[(size_t)MAXE * 32];
__device__ float g_aw[MAXE];
__device__ float g_logits[MAXE];
__device__ float g_Acat[(size_t)MAXN * 288];
__device__ int   g_rowstart[MAXN + 1];
__device__ float g_C1[32 * 128];
__device__ float g_C2[32 * 128];
__device__ float g_C3[32 * 128];
__device__ float g_cvec[128];

// ---------------- helpers ----------------
__device__ __forceinline__ unsigned long long pk2(float x, float y) {
    unsigned long long r;
    asm("mov.b64 %0, {%1, %2};" : "=l"(r) : "f"(x), "f"(y));
    return r;
}
__device__ __forceinline__ unsigned long long ffma2(unsigned long long a,
                                                    unsigned long long b,
                                                    unsigned long long c) {
    unsigned long long d;
    asm("fma.rn.f32x2 %0, %1, %2, %3;" : "=l"(d) : "l"(a), "l"(b), "l"(c));
    return d;
}
__device__ __forceinline__ void upk2(float& lo, float& hi, unsigned long long v) {
    asm("mov.b64 {%0, %1}, %2;" : "=f"(lo), "=f"(hi) : "l"(v));
}
__device__ __forceinline__ void cp16(unsigned int dst_smem, const void* src, bool pred) {
    int sz = pred ? 16 : 0;
    asm volatile("cp.async.ca.shared.global [%0], [%1], 16, %2;"
                 :: "r"(dst_smem), "l"(src), "r"(sz));
}
__device__ __forceinline__ void tf32split(float x, unsigned& hi, unsigned& lo) {
    asm("cvt.rna.tf32.f32 %0, %1;" : "=r"(hi) : "f"(x));
    lo = __float_as_uint(x - __uint_as_float(hi));
}
__device__ __forceinline__ void mma8(float* d, const unsigned* a, unsigned b0, unsigned b1) {
    asm volatile(
        "mma.sync.aligned.m16n8k8.row.col.f32.tf32.tf32.f32 "
        "{%0,%1,%2,%3}, {%4,%5,%6,%7}, {%8,%9}, {%0,%1,%2,%3};"
        : "+f"(d[0]), "+f"(d[1]), "+f"(d[2]), "+f"(d[3])
        : "r"(a[0]), "r"(a[1]), "r"(a[2]), "r"(a[3]), "r"(b0), "r"(b1));
}

// ---------------- K0: segment boundaries (dst sorted) ----------------
__global__ void rowstart_kernel(const int* __restrict__ dst, int E, int Nn) {
    int n = blockIdx.x * blockDim.x + threadIdx.x;
    if (n > Nn) return;
    int lo = 0, hi = E;
    while (lo < hi) {
        int mid = (lo + hi) >> 1;
        if (dst[mid] < n) lo = mid + 1; else hi = mid;
    }
    g_rowstart[n] = lo;
}

// ---------------- prep: combined 32x128 matrices + BN fold ----------------
__global__ void prep_cmat(const float* __restrict__ W3,
                          const float* __restrict__ Wag3,
                          const float* __restrict__ Wee,
                          const float* __restrict__ gamma, const float* __restrict__ beta,
                          const float* __restrict__ mean,  const float* __restrict__ var) {
    int c = threadIdx.x;  // 128
    __shared__ float sWee[1024];
    __shared__ float ssc[32];
    for (int i = c; i < 1024; i += 128) sWee[i] = Wee[i];
    if (c < 32) ssc[c] = gamma[c] * rsqrtf(var[c] + 1e-5f);
    __syncthreads();
    for (int k = 0; k < 32; k++) {
        float a3 = 0.f, a1 = 0.f, a2 = 0.f;
        for (int j = 0; j < 32; j++) {
            float wk = sWee[k * 32 + j];
            a3 = fmaf(wk, W3[j * 128 + c], a3);
            a1 = fmaf(wk, Wag3[j * 128 + c] * ssc[j], a1);
            a2 = fmaf(wk, Wag3[(32 + j) * 128 + c], a2);
        }
        g_C3[k * 128 + c] = a3;
        g_C1[k * 128 + c] = a1;
        g_C2[k * 128 + c] = a2;
    }
    float cv = 0.f;
    for (int j = 0; j < 32; j++)
        cv = fmaf(beta[j] - mean[j] * ssc[j], Wag3[j * 128 + c], cv);
    g_cvec[c] = cv;
}

// ---------------- gemm_v6 core (R10): 3xTF32 mma, cp.async dbuf -------------
#define ABUF 4608   // 128*36
#define BBUF 4352   // 32*136
#define BUFSZ (ABUF + BBUF)
__device__ __forceinline__ void gemm_core(const float* __restrict__ A,
                                          const float* __restrict__ B,
                                          const float* __restrict__ bias,
                                          float* __restrict__ C,
                                          int M, int K, int mode, float* sm) {
    int tid = threadIdx.x;
    int lane = tid & 31;
    int wid = tid >> 5;
    int warp_m = wid >> 1;
    int warp_n = wid & 1;
    int g = lane >> 2;
    int t = lane & 3;
    int row0 = blockIdx.x * 128;
    unsigned int smem_base = (unsigned int)__cvta_generic_to_shared(sm);

    float acc[2][8][4];
#pragma unroll
    for (int mi = 0; mi < 2; mi++)
#pragma unroll
        for (int ni = 0; ni < 8; ni++)
#pragma unroll
            for (int q = 0; q < 4; q++) acc[mi][ni][q] = 0.f;

    int nch = K >> 5;

#pragma unroll
    for (int i = 0; i < 4; i++) {
        int idx = tid + 256 * i;
        int r = idx >> 3, kg = idx & 7;
        cp16(smem_base + (r * 36 + kg * 4) * 4,
             &A[(size_t)(row0 + r) * K + kg * 4], row0 + r < M);
    }
#pragma unroll
    for (int i = 0; i < 4; i++) {
        int idx = tid + 256 * i;
        int k = idx >> 5, cg = idx & 31;
        cp16(smem_base + (ABUF + k * 136 + cg * 4) * 4,
             &B[(size_t)k * 128 + cg * 4], true);
    }
    asm volatile("cp.async.commit_group;");

    for (int c = 0; c < nch; c++) {
        int buf = c & 1;
        if (c + 1 < nch) {
            int kc = (c + 1) * 32;
            unsigned int boff = smem_base + ((c + 1) & 1) * BUFSZ * 4;
#pragma unroll
            for (int i = 0; i < 4; i++) {
                int idx = tid + 256 * i;
                int r = idx >> 3, kg = idx & 7;
                cp16(boff + (r * 36 + kg * 4) * 4,
                     &A[(size_t)(row0 + r) * K + kc + kg * 4], row0 + r < M);
            }
#pragma unroll
            for (int i = 0; i < 4; i++) {
                int idx = tid + 256 * i;
                int k = idx >> 5, cg = idx & 31;
                cp16(boff + (ABUF + k * 136 + cg * 4) * 4,
                     &B[(size_t)(kc + k) * 128 + cg * 4], true);
            }
            asm volatile("cp.async.commit_group;");
            asm volatile("cp.async.wait_group 1;");
        } else {
            asm volatile("cp.async.wait_group 0;");
        }
        __syncthreads();

        const float* As = sm + buf * BUFSZ;
        const float* Bs = sm + buf * BUFSZ + ABUF;

#pragma unroll
        for (int k8 = 0; k8 < 4; k8++) {
            int k = k8 * 8;
            unsigned ahi[2][4], alo[2][4];
#pragma unroll
            for (int mi = 0; mi < 2; mi++) {
                int r0 = warp_m * 32 + mi * 16;
                tf32split(As[(r0 + g) * 36 + k + t],         ahi[mi][0], alo[mi][0]);
                tf32split(As[(r0 + g + 8) * 36 + k + t],     ahi[mi][1], alo[mi][1]);
                tf32split(As[(r0 + g) * 36 + k + t + 4],     ahi[mi][2], alo[mi][2]);
                tf32split(As[(r0 + g + 8) * 36 + k + t + 4], ahi[mi][3], alo[mi][3]);
            }
#pragma unroll
            for (int ni = 0; ni < 8; ni++) {
                int cb = warp_n * 64 + ni * 8 + g;
                float bv0 = Bs[(k + t) * 136 + cb];
                float bv1 = Bs[(k + t + 4) * 136 + cb];
                unsigned bh0, bl0, bh1, bl1;
                tf32split(bv0, bh0, bl0);
                tf32split(bv1, bh1, bl1);
#pragma unroll
                for (int mi = 0; mi < 2; mi++) {
                    mma8(acc[mi][ni], ahi[mi], bh0, bh1);
                    mma8(acc[mi][ni], ahi[mi], bl0, bl1);
                    mma8(acc[mi][ni], alo[mi], bh0, bh1);
                }
            }
        }
        __syncthreads();
    }

    float2 bias2[8];
#pragma unroll
    for (int ni = 0; ni < 8; ni++) {
        int col = warp_n * 64 + ni * 8 + 2 * t;
        bias2[ni] = bias ? *(const float2*)&bias[col] : make_float2(0.f, 0.f);
    }
#pragma unroll
    for (int mi = 0; mi < 2; mi++) {
        int rbase = row0 + warp_m * 32 + mi * 16;
#pragma unroll
        for (int h = 0; h < 2; h++) {
            int row = rbase + g + h * 8;
            if (row < M) {
                bool sub = (mode == 1) && (g_rowstart[row + 1] == g_rowstart[row]);
#pragma unroll
                for (int ni = 0; ni < 8; ni++) {
                    int col = warp_n * 64 + ni * 8 + 2 * t;
                    float2 v;
                    if (sub) {
                        v = *(const float2*)&g_hn[(size_t)row * 128 + col];
                    } else {
                        v.x = acc[mi][ni][h * 2 + 0] + bias2[ni].x;
                        v.y = acc[mi][ni][h * 2 + 1] + bias2[ni].y;
                    }
                    *(float2*)&C[(size_t)row * 128 + col] = v;
                }
            }
        }
    }
}

__global__ __launch_bounds__(256, 2)
void gemm_v6(const float* __restrict__ A, const float* __restrict__ B,
             const float* __restrict__ bias, float* __restrict__ C,
             int M, int K, int mode) {
    extern __shared__ float sm[];
    gemm_core(A, B, bias, C, M, K, mode, sm);
}

// dual-B: blockIdx.y picks (B0->C0) or (B1->C1); same A, no bias, mode 0.
__global__ __launch_bounds__(256, 2)
void gemm_v6_dual(const float* __restrict__ A,
                  const float* __restrict__ B0, const float* __restrict__ B1,
                  float* __restrict__ C0, float* __restrict__ C1,
                  int M, int K) {
    extern __shared__ float sm[];
    const float* B = blockIdx.y ? B1 : B0;
    float* C = blockIdx.y ? C1 : C0;
    gemm_core(A, B, nullptr, C, M, K, 0, sm);
}

// ---------------- fuse_gemm_v2: merged k_embed + fuse -----------------------
__global__ __launch_bounds__(256, 2)
void fuse_gemm_v2(const float* __restrict__ w,
                  const int* __restrict__ src, const int* __restrict__ dst,
                  const float* __restrict__ Wee, const float* __restrict__ Wsf,
                  const float* __restrict__ bif, const float* __restrict__ Wattn,
                  float* __restrict__ sat_out, int E) {
    __shared__ float As[32][132];
    __shared__ float Bs[32][132];
    __shared__ float Bse[32][36];
    __shared__ float sWsf[32];
    __shared__ float part[128][17];
    __shared__ float ss[128];
    int tid = threadIdx.x;
    int tx = tid & 15;
    int ty = tid >> 4;
    int row0 = blockIdx.x * 128;

    unsigned long long acc[2][4][2][2];
    unsigned long long oacc[2][4];
#pragma unroll
    for (int a = 0; a < 2; a++)
#pragma unroll
        for (int b = 0; b < 4; b++) {
            oacc[a][b] = 0ull;
#pragma unroll
            for (int c = 0; c < 2; c++)
#pragma unroll
                for (int d = 0; d < 2; d++) acc[a][b][c][d] = 0ull;
        }

#pragma unroll
    for (int i = 0; i < 4; i++) {
        int e = tid + 256 * i;
        int r = e >> 3;
        int kg = e & 7;
        float4 v = make_float4(0.f, 0.f, 0.f, 0.f);
        if (row0 + r < E)
            v = *(const float4*)&w[(size_t)(row0 + r) * 32 + kg * 4];
        As[kg * 4 + 0][r] = v.x;
        As[kg * 4 + 1][r] = v.y;
        As[kg * 4 + 2][r] = v.z;
        As[kg * 4 + 3][r] = v.w;
    }
#pragma unroll
    for (int i = 0; i < 4; i++) {
        int e = tid + 256 * i;
        int k = e >> 5;
        int cg = e & 31;
        *(float4*)&Bs[k][cg * 4] = *(const float4*)&g_C3[k * 128 + cg * 4];
    }
    {
        int k = tid >> 3, c4 = tid & 7;
        *(float4*)&Bse[k][c4 * 4] = *(const float4*)&Wee[k * 32 + c4 * 4];
    }
    if (tid < 32) sWsf[tid] = Wsf[tid];
    __syncthreads();

#pragma unroll
    for (int k = 0; k < 32; k++) {
        float4 af0 = *(const float4*)&As[k][ty * 4];
        float4 af1 = *(const float4*)&As[k][64 + ty * 4];
        ulonglong2 b0 = *(const ulonglong2*)&Bs[k][tx * 4];
        ulonglong2 b1 = *(const ulonglong2*)&Bs[k][64 + tx * 4];
        unsigned long long be = *(const unsigned long long*)&Bse[k][tx * 2];
        float av[2][4] = {{af0.x, af0.y, af0.z, af0.w}, {af1.x, af1.y, af1.z, af1.w}};
#pragma unroll
        for (int mi = 0; mi < 2; mi++)
#pragma unroll
            for (int j = 0; j < 4; j++) {
                unsigned long long ap = pk2(av[mi][j], av[mi][j]);
                acc[mi][j][0][0] = ffma2(ap, b0.x, acc[mi][j][0][0]);
                acc[mi][j][0][1] = ffma2(ap, b0.y, acc[mi][j][0][1]);
                acc[mi][j][1][0] = ffma2(ap, b1.x, acc[mi][j][1][0]);
                acc[mi][j][1][1] = ffma2(ap, b1.y, acc[mi][j][1][1]);
                oacc[mi][j]      = ffma2(ap, be,  oacc[mi][j]);
            }
    }
    __syncthreads();

    float sfl = sWsf[tx * 2], sfh = sWsf[tx * 2 + 1];
    float4 bf0 = *(const float4*)&bif[tx * 4];
    float4 bf1 = *(const float4*)&bif[64 + tx * 4];
    float4 wa0 = *(const float4*)&Wattn[tx * 4];
    float4 wa1 = *(const float4*)&Wattn[64 + tx * 4];

#pragma unroll
    for (int mi = 0; mi < 2; mi++)
#pragma unroll
        for (int j = 0; j < 4; j++) {
            int rl = mi * 64 + ty * 4 + j;
            int row = row0 + rl;
            float olo, ohi;
            upk2(olo, ohi, oacc[mi][j]);
            float llo = olo > 0.f ? olo : 0.1f * olo;
            float lhi = ohi > 0.f ? ohi : 0.1f * ohi;
            float ps = fmaf(llo, sfl, lhi * sfh);
            ps += __shfl_xor_sync(0xffffffffu, ps, 1);
            ps += __shfl_xor_sync(0xffffffffu, ps, 2);
            ps += __shfl_xor_sync(0xffffffffu, ps, 4);
            ps += __shfl_xor_sync(0xffffffffu, ps, 8);
            float sE = ps;
            if (tx == 0) ss[rl] = sE;

            float partial = 0.f;
            if (row < E) {
                float2 owv = make_float2(olo, ohi);
                *(float2*)&g_ow[(size_t)row * 32 + tx * 2] = owv;
                float2 sow = make_float2(sE * olo, sE * ohi);
                *(float2*)&sat_out[(size_t)row * 288 + 256 + tx * 2] = sow;

                int s = src[row], d = dst[row];
                float4 p1a = *(const float4*)&g_P1[(size_t)s * 128 + tx * 4];
                float4 p2a = *(const float4*)&g_P2[(size_t)d * 128 + tx * 4];
                float4 p1b = *(const float4*)&g_P1[(size_t)s * 128 + 64 + tx * 4];
                float4 p2b = *(const float4*)&g_P2[(size_t)d * 128 + 64 + tx * 4];
                float z[8];
                upk2(z[0], z[1], acc[mi][j][0][0]);
                upk2(z[2], z[3], acc[mi][j][0][1]);
                upk2(z[4], z[5], acc[mi][j][1][0]);
                upk2(z[6], z[7], acc[mi][j][1][1]);
                z[0] = fmaf(sE, z[0], p1a.x + p2a.x + bf0.x);
                z[1] = fmaf(sE, z[1], p1a.y + p2a.y + bf0.y);
                z[2] = fmaf(sE, z[2], p1a.z + p2a.z + bf0.z);
                z[3] = fmaf(sE, z[3], p1a.w + p2a.w + bf0.w);
                z[4] = fmaf(sE, z[4], p1b.x + p2b.x + bf1.x);
                z[5] = fmaf(sE, z[5], p1b.y + p2b.y + bf1.y);
                z[6] = fmaf(sE, z[6], p1b.z + p2b.z + bf1.z);
                z[7] = fmaf(sE, z[7], p1b.w + p2b.w + bf1.w);
                float wv[8] = {wa0.x, wa0.y, wa0.z, wa0.w, wa1.x, wa1.y, wa1.z, wa1.w};
#pragma unroll
                for (int c = 0; c < 8; c++) {
                    float l = z[c] > 0.f ? z[c] : 0.1f * z[c];
                    partial = fmaf(l, wv[c], partial);
                }
                size_t so = (size_t)row * 288;
                *(float4*)&sat_out[so + tx * 4]        = *(const float4*)&g_hn[(size_t)s * 128 + tx * 4];
                *(float4*)&sat_out[so + 64 + tx * 4]   = *(const float4*)&g_hn[(size_t)s * 128 + 64 + tx * 4];
                *(float4*)&sat_out[so + 128 + tx * 4]  = *(const float4*)&g_hn[(size_t)d * 128 + tx * 4];
                *(float4*)&sat_out[so + 192 + tx * 4]  = *(const float4*)&g_hn[(size_t)d * 128 + 64 + tx * 4];
            }
            part[rl][tx] = partial;
        }
    __syncthreads();
    if (tid < 128) {
        int row = row0 + tid;
        if (row < E) {
            float v = 0.f;
#pragma unroll
            for (int i = 0; i < 16; i++) v += part[tid][i];
            g_logits[row] = v;
            g_aw[row] = v * ss[tid];
        }
    }
}

// ---------------- segment softmax + aggregate + hn copy (warp per node) -----
__global__ void segment_kernel(const int* __restrict__ src, int Nn) {
    int warp = (blockIdx.x * blockDim.x + threadIdx.x) >> 5;
    int lane = threadIdx.x & 31;
    if (warp >= Nn) return;
    int s0 = g_rowstart[warp], s1 = g_rowstart[warp + 1];
    float acc[5] = {0.f, 0.f, 0.f, 0.f, 0.f};
    if (s1 > s0) {
        float m = -INFINITY;
        for (int e = s0 + lane; e < s1; e += 32) m = fmaxf(m, g_logits[e]);
#pragma unroll
        for (int o = 16; o; o >>= 1) m = fmaxf(m, __shfl_xor_sync(0xffffffffu, m, o));
        float den = 0.f;
        for (int e = s0 + lane; e < s1; e += 32) den += expf(g_logits[e] - m);
#pragma unroll
        for (int o = 16; o; o >>= 1) den += __shfl_xor_sync(0xffffffffu, den, o);
        float inv = 1.0f / den;
        for (int e = s0; e < s1; e++) {
            float alpha = expf(g_logits[e] - m) * inv;
            int sidx = src[e];
#pragma unroll
            for (int i = 0; i < 4; i++)
                acc[i] = fmaf(alpha, g_hn[(size_t)sidx * 128 + lane + 32 * i], acc[i]);
            acc[4] = fmaf(alpha * g_aw[e], g_ow[(size_t)e * 32 + lane], acc[4]);
        }
    }
#pragma unroll
    for (int i = 0; i < 4; i++) g_Acat[(size_t)warp * 288 + lane + 32 * i] = acc[i];
    g_Acat[(size_t)warp * 288 + 128 + lane] = acc[4];
    float4 hv = *(const float4*)&g_hn[(size_t)warp * 128 + lane * 4];
    *(float4*)&g_Acat[(size_t)warp * 288 + 160 + lane * 4] = hv;
}

// ---------------- wout_gemm (R10 FFMA version) -------------------------------
__global__ __launch_bounds__(256, 2)
void wout_gemm(const float* __restrict__ w, const int* __restrict__ src,
               const int* __restrict__ dst, float* __restrict__ wout, int E) {
    __shared__ float As[32][132];
    __shared__ float Bs[32][132];
    __shared__ float saw[128];
    int tid = threadIdx.x;
    int tx = tid & 15;
    int ty = tid >> 4;
    int row0 = blockIdx.x * 128;

    if (tid < 128) saw[tid] = (row0 + tid < E) ? g_aw[row0 + tid] : 0.f;

    unsigned long long acc[2][4][2][2];
#pragma unroll
    for (int a = 0; a < 2; a++)
#pragma unroll
        for (int b = 0; b < 4; b++)
#pragma unroll
            for (int c = 0; c < 2; c++)
#pragma unroll
                for (int d = 0; d < 2; d++) acc[a][b][c][d] = 0ull;

#pragma unroll
    for (int chunk = 0; chunk < 2; chunk++) {
        const float* Bsrc = chunk == 0 ? g_C2 : g_C1;
        if (chunk) __syncthreads();
#pragma unroll
        for (int i = 0; i < 4; i++) {
            int e = tid + 256 * i;
            int r = e >> 3;
            int kg = e & 7;
            float4 v = make_float4(0.f, 0.f, 0.f, 0.f);
            if (row0 + r < E)
                v = *(const float4*)&w[(size_t)(row0 + r) * 32 + kg * 4];
            float sc = chunk == 0 ? 1.f : saw[r];
            As[kg * 4 + 0][r] = sc * v.x;
            As[kg * 4 + 1][r] = sc * v.y;
            As[kg * 4 + 2][r] = sc * v.z;
            As[kg * 4 + 3][r] = sc * v.w;
        }
#pragma unroll
        for (int i = 0; i < 4; i++) {
            int e = tid + 256 * i;
            int k = e >> 5;
            int cg = e & 31;
            *(float4*)&Bs[k][cg * 4] = *(const float4*)&Bsrc[k * 128 + cg * 4];
        }
        __syncthreads();
#pragma unroll
        for (int k = 0; k < 32; k++) {
            float4 af0 = *(const float4*)&As[k][ty * 4];
            float4 af1 = *(const float4*)&As[k][64 + ty * 4];
            ulonglong2 b0 = *(const ulonglong2*)&Bs[k][tx * 4];
            ulonglong2 b1 = *(const ulonglong2*)&Bs[k][64 + tx * 4];
            float av[2][4] = {{af0.x, af0.y, af0.z, af0.w}, {af1.x, af1.y, af1.z, af1.w}};
#pragma unroll
            for (int mi = 0; mi < 2; mi++)
#pragma unroll
                for (int j = 0; j < 4; j++) {
                    unsigned long long ap = pk2(av[mi][j], av[mi][j]);
                    acc[mi][j][0][0] = ffma2(ap, b0.x, acc[mi][j][0][0]);
                    acc[mi][j][0][1] = ffma2(ap, b0.y, acc[mi][j][0][1]);
                    acc[mi][j][1][0] = ffma2(ap, b1.x, acc[mi][j][1][0]);
                    acc[mi][j][1][1] = ffma2(ap, b1.y, acc[mi][j][1][1]);
                }
        }
    }
    float4 cv0 = *(const float4*)&g_cvec[tx * 4];
    float4 cv1 = *(const float4*)&g_cvec[64 + tx * 4];
#pragma unroll
    for (int mi = 0; mi < 2; mi++)
#pragma unroll
        for (int j = 0; j < 4; j++) {
            int row = row0 + mi * 64 + ty * 4 + j;
            if (row < E) {
                int s = src[row], d = dst[row];
                float4 q1a = *(const float4*)&g_Q1[(size_t)s * 128 + tx * 4];
                float4 q2a = *(const float4*)&g_Q2[(size_t)d * 128 + tx * 4];
                float4 q1b = *(const float4*)&g_Q1[(size_t)s * 128 + 64 + tx * 4];
                float4 q2b = *(const float4*)&g_Q2[(size_t)d * 128 + 64 + tx * 4];
                float z[8];
                upk2(z[0], z[1], acc[mi][j][0][0]);
                upk2(z[2], z[3], acc[mi][j][0][1]);
                upk2(z[4], z[5], acc[mi][j][1][0]);
                upk2(z[6], z[7], acc[mi][j][1][1]);
                float4 o0, o1;
                o0.x = z[0] + q1a.x + q2a.x + cv0.x;
                o0.y = z[1] + q1a.y + q2a.y + cv0.y;
                o0.z = z[2] + q1a.z + q2a.z + cv0.z;
                o0.w = z[3] + q1a.w + q2a.w + cv0.w;
                o1.x = z[4] + q1b.x + q2b.x + cv1.x;
                o1.y = z[5] + q1b.y + q2b.y + cv1.y;
                o1.z = z[6] + q1b.z + q2b.z + cv1.z;
                o1.w = z[7] + q1b.w + q2b.w + cv1.w;
                *(float4*)&wout[(size_t)row * 128 + tx * 4] = o0;
                *(float4*)&wout[(size_t)row * 128 + 64 + tx * 4] = o1;
            }
        }
}

// ---------------- launch ----------------
extern "C" void kernel_launch(void* const* d_in, const int* in_sizes, int n_in,
                              void* d_out, int out_size) {
    const float* h        = (const float*)d_in[0];
    const float* w        = (const float*)d_in[1];
    const int*   src      = (const int*)d_in[2];
    const int*   dst      = (const int*)d_in[3];
    const float* W_en     = (const float*)d_in[4];
    const float* W_attn   = (const float*)d_in[5];
    const float* W_if     = (const float*)d_in[6];
    const float* b_if     = (const float*)d_in[7];
    const float* W_ee     = (const float*)d_in[8];
    const float* W_sf     = (const float*)d_in[9];
    const float* W_conc   = (const float*)d_in[10];
    const float* b_conc   = (const float*)d_in[11];
    const float* bn_gamma = (const float*)d_in[12];
    const float* bn_beta  = (const float*)d_in[13];
    const float* bn_mean  = (const float*)d_in[14];
    const float* bn_var   = (const float*)d_in[15];
    const float* W_ag     = (const float*)d_in[16];

    int Nn = in_sizes[0] / 128;
    int E  = in_sizes[2];

    float* out_hnew = (float*)d_out;
    float* out_wout = out_hnew + (size_t)Nn * 128;
    float* out_sat  = out_wout + (size_t)E * 128;

    float *hn_p, *P1_p, *P2_p, *Q1_p, *Q2_p, *Acat_p;
    cudaGetSymbolAddress((void**)&hn_p,   g_hn);
    cudaGetSymbolAddress((void**)&P1_p,   g_P1);
    cudaGetSymbolAddress((void**)&P2_p,   g_P2);
    cudaGetSymbolAddress((void**)&Q1_p,   g_Q1);
    cudaGetSymbolAddress((void**)&Q2_p,   g_Q2);
    cudaGetSymbolAddress((void**)&Acat_p, g_Acat);

    const int G6_SMEM = 2 * BUFSZ * 4;   // 71680 bytes
    cudaFuncSetAttribute(gemm_v6, cudaFuncAttributeMaxDynamicSharedMemorySize, G6_SMEM);
    cudaFuncSetAttribute(gemm_v6_dual, cudaFuncAttributeMaxDynamicSharedMemorySize, G6_SMEM);

    int gbN = (Nn + 127) / 128;
    int gbE = (E + 127) / 128;

    rowstart_kernel<<<(Nn + 256) / 256, 256>>>(dst, E, Nn);
    prep_cmat<<<1, 128>>>(W_if + 256 * 128, W_ag + 256 * 128, W_ee,
                          bn_gamma, bn_beta, bn_mean, bn_var);
    gemm_v6<<<gbN, 256, G6_SMEM>>>(h, W_en, nullptr, hn_p, Nn, 128, 0);
    gemm_v6_dual<<<dim3(gbN, 2), 256, G6_SMEM>>>(hn_p, W_if, W_if + 128 * 128,
                                                 P1_p, P2_p, Nn, 128);
    fuse_gemm_v2<<<gbE, 256>>>(w, src, dst, W_ee, W_sf, b_if, W_attn, out_sat, E);
    segment_kernel<<<(Nn + 7) / 8, 256>>>(src, Nn);
    gemm_v6<<<gbN, 256, G6_SMEM>>>(Acat_p, W_conc, b_conc, out_hnew, Nn, 288, 1);
    gemm_v6_dual<<<dim3(gbN, 2), 256, G6_SMEM>>>(out_hnew, W_ag, W_ag + 128 * 128,
                                                 Q1_p, Q2_p, Nn, 128);
    wout_gemm<<<gbE, 256>>>(w, src, dst, out_wout, E);
}

// round 15
// speedup vs baseline: 1.0685x; 1.0030x over previous
#include <cuda_runtime.h>
#include <cuda_bf16.h>
#include <math.h>

#define MAXN 50000
#define MAXE 400000

// ---------------- scratch (device globals) ----------------
__device__ float g_hn[MAXN * 128];
__device__ float g_P1[MAXN * 128];
__device__ float g_P2[MAXN * 128];
__device__ float g_Q1[MAXN * 128];
__device__ float g_Q2[MAXN * 128];
__device__ float g_ow[(size_t)MAXE * 32];
__device__ float g_aw[MAXE];
__device__ float g_logits[MAXE];
__device__ float g_hagg[(size_t)MAXN * 160];
__device__ int   g_rowstart[MAXN + 1];
__device__ float g_C1[32 * 128];
__device__ float g_C2[32 * 128];
__device__ float g_C3[32 * 128];
__device__ float g_cvec[128];

// ---------------- helpers ----------------
__device__ __forceinline__ unsigned long long pk2(float x, float y) {
    unsigned long long r;
    asm("mov.b64 %0, {%1, %2};" : "=l"(r) : "f"(x), "f"(y));
    return r;
}
__device__ __forceinline__ unsigned long long ffma2(unsigned long long a,
                                                    unsigned long long b,
                                                    unsigned long long c) {
    unsigned long long d;
    asm("fma.rn.f32x2 %0, %1, %2, %3;" : "=l"(d) : "l"(a), "l"(b), "l"(c));
    return d;
}
__device__ __forceinline__ void upk2(float& lo, float& hi, unsigned long long v) {
    asm("mov.b64 {%0, %1}, %2;" : "=f"(lo), "=f"(hi) : "l"(v));
}
__device__ __forceinline__ void cp16(unsigned int dst_smem, const void* src, bool pred) {
    int sz = pred ? 16 : 0;
    asm volatile("cp.async.ca.shared.global [%0], [%1], 16, %2;"
                 :: "r"(dst_smem), "l"(src), "r"(sz));
}
__device__ __forceinline__ void tf32split(float x, unsigned& hi, unsigned& lo) {
    asm("cvt.rna.tf32.f32 %0, %1;" : "=r"(hi) : "f"(x));
    lo = __float_as_uint(x - __uint_as_float(hi));
}
__device__ __forceinline__ void mma8(float* d, const unsigned* a, unsigned b0, unsigned b1) {
    asm volatile(
        "mma.sync.aligned.m16n8k8.row.col.f32.tf32.tf32.f32 "
        "{%0,%1,%2,%3}, {%4,%5,%6,%7}, {%8,%9}, {%0,%1,%2,%3};"
        : "+f"(d[0]), "+f"(d[1]), "+f"(d[2]), "+f"(d[3])
        : "r"(a[0]), "r"(a[1]), "r"(a[2]), "r"(a[3]), "r"(b0), "r"(b1));
}

// ---------------- K0: segment boundaries (dst sorted) ----------------
__global__ void rowstart_kernel(const int* __restrict__ dst, int E, int Nn) {
    int n = blockIdx.x * blockDim.x + threadIdx.x;
    if (n > Nn) return;
    int lo = 0, hi = E;
    while (lo < hi) {
        int mid = (lo + hi) >> 1;
        if (dst[mid] < n) lo = mid + 1; else hi = mid;
    }
    g_rowstart[n] = lo;
}

// ---------------- prep: combined 32x128 matrices + BN fold ----------------
__global__ void prep_cmat(const float* __restrict__ W3,
                          const float* __restrict__ Wag3,
                          const float* __restrict__ Wee,
                          const float* __restrict__ gamma, const float* __restrict__ beta,
                          const float* __restrict__ mean,  const float* __restrict__ var) {
    int c = threadIdx.x;  // 128
    __shared__ float sWee[1024];
    __shared__ float ssc[32];
    for (int i = c; i < 1024; i += 128) sWee[i] = Wee[i];
    if (c < 32) ssc[c] = gamma[c] * rsqrtf(var[c] + 1e-5f);
    __syncthreads();
    for (int k = 0; k < 32; k++) {
        float a3 = 0.f, a1 = 0.f, a2 = 0.f;
        for (int j = 0; j < 32; j++) {
            float wk = sWee[k * 32 + j];
            a3 = fmaf(wk, W3[j * 128 + c], a3);
            a1 = fmaf(wk, Wag3[j * 128 + c] * ssc[j], a1);
            a2 = fmaf(wk, Wag3[(32 + j) * 128 + c], a2);
        }
        g_C3[k * 128 + c] = a3;
        g_C1[k * 128 + c] = a1;
        g_C2[k * 128 + c] = a2;
    }
    float cv = 0.f;
    for (int j = 0; j < 32; j++)
        cv = fmaf(beta[j] - mean[j] * ssc[j], Wag3[j * 128 + c], cv);
    g_cvec[c] = cv;
}

// ---------------- gemm_v6 core: 3xTF32 mma, cp.async dbuf -------------------
#define ABUF 4608   // 128*36
#define BBUF 4352   // 32*136
#define BUFSZ (ABUF + BBUF)

// A-chunk loader: conc mode reads chunks 0..4 from g_hagg (stride 160),
// chunks 5..8 from g_hn (stride 128).
__device__ __forceinline__ const float* conc_src(int chunk, int& stride, int& coff) {
    if (chunk < 5) { stride = 160; coff = chunk * 32; return g_hagg; }
    stride = 128; coff = (chunk - 5) * 32; return g_hn;
}

template <int CONC>
__device__ __forceinline__ void gemm_core(const float* __restrict__ A,
                                          const float* __restrict__ B,
                                          const float* __restrict__ bias,
                                          float* __restrict__ C,
                                          int M, int K, float* sm) {
    int tid = threadIdx.x;
    int lane = tid & 31;
    int wid = tid >> 5;
    int warp_m = wid >> 1;
    int warp_n = wid & 1;
    int g = lane >> 2;
    int t = lane & 3;
    int row0 = blockIdx.x * 128;
    unsigned int smem_base = (unsigned int)__cvta_generic_to_shared(sm);

    float acc[2][8][4];
#pragma unroll
    for (int mi = 0; mi < 2; mi++)
#pragma unroll
        for (int ni = 0; ni < 8; ni++)
#pragma unroll
            for (int q = 0; q < 4; q++) acc[mi][ni][q] = 0.f;

    int nch = K >> 5;

    {
        const float* Asrc = A; int astr = K, coff = 0;
        if (CONC) Asrc = conc_src(0, astr, coff);
#pragma unroll
        for (int i = 0; i < 4; i++) {
            int idx = tid + 256 * i;
            int r = idx >> 3, kg = idx & 7;
            cp16(smem_base + (r * 36 + kg * 4) * 4,
                 &Asrc[(size_t)(row0 + r) * astr + coff + kg * 4], row0 + r < M);
        }
#pragma unroll
        for (int i = 0; i < 4; i++) {
            int idx = tid + 256 * i;
            int k = idx >> 5, cg = idx & 31;
            cp16(smem_base + (ABUF + k * 136 + cg * 4) * 4,
                 &B[(size_t)k * 128 + cg * 4], true);
        }
        asm volatile("cp.async.commit_group;");
    }

    for (int c = 0; c < nch; c++) {
        int buf = c & 1;
        if (c + 1 < nch) {
            const float* Asrc = A; int astr = K, coff = (c + 1) * 32;
            if (CONC) Asrc = conc_src(c + 1, astr, coff);
            int kc = (c + 1) * 32;
            unsigned int boff = smem_base + ((c + 1) & 1) * BUFSZ * 4;
#pragma unroll
            for (int i = 0; i < 4; i++) {
                int idx = tid + 256 * i;
                int r = idx >> 3, kg = idx & 7;
                cp16(boff + (r * 36 + kg * 4) * 4,
                     &Asrc[(size_t)(row0 + r) * astr + coff + kg * 4], row0 + r < M);
            }
#pragma unroll
            for (int i = 0; i < 4; i++) {
                int idx = tid + 256 * i;
                int k = idx >> 5, cg = idx & 31;
                cp16(boff + (ABUF + k * 136 + cg * 4) * 4,
                     &B[(size_t)(kc + k) * 128 + cg * 4], true);
            }
            asm volatile("cp.async.commit_group;");
            asm volatile("cp.async.wait_group 1;");
        } else {
            asm volatile("cp.async.wait_group 0;");
        }
        __syncthreads();

        const float* As = sm + buf * BUFSZ;
        const float* Bs = sm + buf * BUFSZ + ABUF;

#pragma unroll
        for (int k8 = 0; k8 < 4; k8++) {
            int k = k8 * 8;
            unsigned ahi[2][4], alo[2][4];
#pragma unroll
            for (int mi = 0; mi < 2; mi++) {
                int r0 = warp_m * 32 + mi * 16;
                tf32split(As[(r0 + g) * 36 + k + t],         ahi[mi][0], alo[mi][0]);
                tf32split(As[(r0 + g + 8) * 36 + k + t],     ahi[mi][1], alo[mi][1]);
                tf32split(As[(r0 + g) * 36 + k + t + 4],     ahi[mi][2], alo[mi][2]);
                tf32split(As[(r0 + g + 8) * 36 + k + t + 4], ahi[mi][3], alo[mi][3]);
            }
#pragma unroll
            for (int ni = 0; ni < 8; ni++) {
                int cb = warp_n * 64 + ni * 8 + g;
                float bv0 = Bs[(k + t) * 136 + cb];
                float bv1 = Bs[(k + t + 4) * 136 + cb];
                unsigned bh0, bl0, bh1, bl1;
                tf32split(bv0, bh0, bl0);
                tf32split(bv1, bh1, bl1);
#pragma unroll
                for (int mi = 0; mi < 2; mi++) {
                    mma8(acc[mi][ni], ahi[mi], bh0, bh1);
                    mma8(acc[mi][ni], ahi[mi], bl0, bl1);
                    mma8(acc[mi][ni], alo[mi], bh0, bh1);
                }
            }
        }
        __syncthreads();
    }

    float2 bias2[8];
#pragma unroll
    for (int ni = 0; ni < 8; ni++) {
        int col = warp_n * 64 + ni * 8 + 2 * t;
        bias2[ni] = bias ? *(const float2*)&bias[col] : make_float2(0.f, 0.f);
    }
#pragma unroll
    for (int mi = 0; mi < 2; mi++) {
        int rbase = row0 + warp_m * 32 + mi * 16;
#pragma unroll
        for (int h = 0; h < 2; h++) {
            int row = rbase + g + h * 8;
            if (row < M) {
                bool sub = CONC && (g_rowstart[row + 1] == g_rowstart[row]);
#pragma unroll
                for (int ni = 0; ni < 8; ni++) {
                    int col = warp_n * 64 + ni * 8 + 2 * t;
                    float2 v;
                    if (sub) {
                        v = *(const float2*)&g_hn[(size_t)row * 128 + col];
                    } else {
                        v.x = acc[mi][ni][h * 2 + 0] + bias2[ni].x;
                        v.y = acc[mi][ni][h * 2 + 1] + bias2[ni].y;
                    }
                    *(float2*)&C[(size_t)row * 128 + col] = v;
                }
            }
        }
    }
}

__global__ __launch_bounds__(256, 2)
void gemm_v6(const float* __restrict__ A, const float* __restrict__ B,
             const float* __restrict__ bias, float* __restrict__ C,
             int M, int K) {
    extern __shared__ float sm[];
    gemm_core<0>(A, B, bias, C, M, K, sm);
}

__global__ __launch_bounds__(256, 2)
void gemm_conc2(const float* __restrict__ B, const float* __restrict__ bias,
                float* __restrict__ C, int M) {
    extern __shared__ float sm[];
    gemm_core<1>(nullptr, B, bias, C, M, 288, sm);
}

// dual-B: blockIdx.y picks (B0->C0) or (B1->C1); same A, no bias.
__global__ __launch_bounds__(256, 2)
void gemm_v6_dual(const float* __restrict__ A,
                  const float* __restrict__ B0, const float* __restrict__ B1,
                  float* __restrict__ C0, float* __restrict__ C1,
                  int M, int K) {
    extern __shared__ float sm[];
    const float* B = blockIdx.y ? B1 : B0;
    float* C = blockIdx.y ? C1 : C0;
    gemm_core<0>(A, B, nullptr, C, M, K, sm);
}

// ---------------- fuse_gemm_v3: merged k_embed + fuse, shfl reductions ------
__global__ __launch_bounds__(256, 2)
void fuse_gemm_v3(const float* __restrict__ w,
                  const int* __restrict__ src, const int* __restrict__ dst,
                  const float* __restrict__ Wee, const float* __restrict__ Wsf,
                  const float* __restrict__ bif, const float* __restrict__ Wattn,
                  float* __restrict__ sat_out, int E) {
    __shared__ float As[32][132];
    __shared__ float Bs[32][132];
    __shared__ float Bse[32][36];
    __shared__ float sWsf[32];
    int tid = threadIdx.x;
    int tx = tid & 15;
    int ty = tid >> 4;
    int row0 = blockIdx.x * 128;

    unsigned long long acc[2][4][2][2];
    unsigned long long oacc[2][4];
#pragma unroll
    for (int a = 0; a < 2; a++)
#pragma unroll
        for (int b = 0; b < 4; b++) {
            oacc[a][b] = 0ull;
#pragma unroll
            for (int c = 0; c < 2; c++)
#pragma unroll
                for (int d = 0; d < 2; d++) acc[a][b][c][d] = 0ull;
        }

#pragma unroll
    for (int i = 0; i < 4; i++) {
        int e = tid + 256 * i;
        int r = e >> 3;
        int kg = e & 7;
        float4 v = make_float4(0.f, 0.f, 0.f, 0.f);
        if (row0 + r < E)
            v = *(const float4*)&w[(size_t)(row0 + r) * 32 + kg * 4];
        As[kg * 4 + 0][r] = v.x;
        As[kg * 4 + 1][r] = v.y;
        As[kg * 4 + 2][r] = v.z;
        As[kg * 4 + 3][r] = v.w;
    }
#pragma unroll
    for (int i = 0; i < 4; i++) {
        int e = tid + 256 * i;
        int k = e >> 5;
        int cg = e & 31;
        *(float4*)&Bs[k][cg * 4] = *(const float4*)&g_C3[k * 128 + cg * 4];
    }
    {
        int k = tid >> 3, c4 = tid & 7;
        *(float4*)&Bse[k][c4 * 4] = *(const float4*)&Wee[k * 32 + c4 * 4];
    }
    if (tid < 32) sWsf[tid] = Wsf[tid];
    __syncthreads();

#pragma unroll
    for (int k = 0; k < 32; k++) {
        float4 af0 = *(const float4*)&As[k][ty * 4];
        float4 af1 = *(const float4*)&As[k][64 + ty * 4];
        ulonglong2 b0 = *(const ulonglong2*)&Bs[k][tx * 4];
        ulonglong2 b1 = *(const ulonglong2*)&Bs[k][64 + tx * 4];
        unsigned long long be = *(const unsigned long long*)&Bse[k][tx * 2];
        float av[2][4] = {{af0.x, af0.y, af0.z, af0.w}, {af1.x, af1.y, af1.z, af1.w}};
#pragma unroll
        for (int mi = 0; mi < 2; mi++)
#pragma unroll
            for (int j = 0; j < 4; j++) {
                unsigned long long ap = pk2(av[mi][j], av[mi][j]);
                acc[mi][j][0][0] = ffma2(ap, b0.x, acc[mi][j][0][0]);
                acc[mi][j][0][1] = ffma2(ap, b0.y, acc[mi][j][0][1]);
                acc[mi][j][1][0] = ffma2(ap, b1.x, acc[mi][j][1][0]);
                acc[mi][j][1][1] = ffma2(ap, b1.y, acc[mi][j][1][1]);
                oacc[mi][j]      = ffma2(ap, be,  oacc[mi][j]);
            }
    }

    float sfl = sWsf[tx * 2], sfh = sWsf[tx * 2 + 1];
    float4 bf0 = *(const float4*)&bif[tx * 4];
    float4 bf1 = *(const float4*)&bif[64 + tx * 4];
    float4 wa0 = *(const float4*)&Wattn[tx * 4];
    float4 wa1 = *(const float4*)&Wattn[64 + tx * 4];

#pragma unroll
    for (int mi = 0; mi < 2; mi++)
#pragma unroll
        for (int j = 0; j < 4; j++) {
            int rl = mi * 64 + ty * 4 + j;
            int row = row0 + rl;
            // ---- s for this row (16-lane half-warp shfl reduce) ----
            float olo, ohi;
            upk2(olo, ohi, oacc[mi][j]);
            float llo = olo > 0.f ? olo : 0.1f * olo;
            float lhi = ohi > 0.f ? ohi : 0.1f * ohi;
            float ps = fmaf(llo, sfl, lhi * sfh);
            ps += __shfl_xor_sync(0xffffffffu, ps, 1);
            ps += __shfl_xor_sync(0xffffffffu, ps, 2);
            ps += __shfl_xor_sync(0xffffffffu, ps, 4);
            ps += __shfl_xor_sync(0xffffffffu, ps, 8);
            float sE = ps;

            float partial = 0.f;
            if (row < E) {
                float2 owv = make_float2(olo, ohi);
                *(float2*)&g_ow[(size_t)row * 32 + tx * 2] = owv;
                float2 sow = make_float2(sE * olo, sE * ohi);
                *(float2*)&sat_out[(size_t)row * 288 + 256 + tx * 2] = sow;

                int s = src[row], d = dst[row];
                float4 p1a = *(const float4*)&g_P1[(size_t)s * 128 + tx * 4];
                float4 p2a = *(const float4*)&g_P2[(size_t)d * 128 + tx * 4];
                float4 p1b = *(const float4*)&g_P1[(size_t)s * 128 + 64 + tx * 4];
                float4 p2b = *(const float4*)&g_P2[(size_t)d * 128 + 64 + tx * 4];
                float z[8];
                upk2(z[0], z[1], acc[mi][j][0][0]);
                upk2(z[2], z[3], acc[mi][j][0][1]);
                upk2(z[4], z[5], acc[mi][j][1][0]);
                upk2(z[6], z[7], acc[mi][j][1][1]);
                z[0] = fmaf(sE, z[0], p1a.x + p2a.x + bf0.x);
                z[1] = fmaf(sE, z[1], p1a.y + p2a.y + bf0.y);
                z[2] = fmaf(sE, z[2], p1a.z + p2a.z + bf0.z);
                z[3] = fmaf(sE, z[3], p1a.w + p2a.w + bf0.w);
                z[4] = fmaf(sE, z[4], p1b.x + p2b.x + bf1.x);
                z[5] = fmaf(sE, z[5], p1b.y + p2b.y + bf1.y);
                z[6] = fmaf(sE, z[6], p1b.z + p2b.z + bf1.z);
                z[7] = fmaf(sE, z[7], p1b.w + p2b.w + bf1.w);
                float wv[8] = {wa0.x, wa0.y, wa0.z, wa0.w, wa1.x, wa1.y, wa1.z, wa1.w};
#pragma unroll
                for (int c = 0; c < 8; c++) {
                    float l = z[c] > 0.f ? z[c] : 0.1f * z[c];
                    partial = fmaf(l, wv[c], partial);
                }
                size_t so = (size_t)row * 288;
                *(float4*)&sat_out[so + tx * 4]        = *(const float4*)&g_hn[(size_t)s * 128 + tx * 4];
                *(float4*)&sat_out[so + 64 + tx * 4]   = *(const float4*)&g_hn[(size_t)s * 128 + 64 + tx * 4];
                *(float4*)&sat_out[so + 128 + tx * 4]  = *(const float4*)&g_hn[(size_t)d * 128 + tx * 4];
                *(float4*)&sat_out[so + 192 + tx * 4]  = *(const float4*)&g_hn[(size_t)d * 128 + 64 + tx * 4];
            }
            // ---- attention logit: 16-lane shfl reduce ----
            partial += __shfl_xor_sync(0xffffffffu, partial, 1);
            partial += __shfl_xor_sync(0xffffffffu, partial, 2);
            partial += __shfl_xor_sync(0xffffffffu, partial, 4);
            partial += __shfl_xor_sync(0xffffffffu, partial, 8);
            if (tx == 0 && row < E) {
                g_logits[row] = partial;
                g_aw[row] = partial * sE;
            }
        }
}

// ---------------- segment softmax + aggregate (warp per node) ---------------
__global__ void segment_kernel(const int* __restrict__ src, int Nn) {
    int warp = (blockIdx.x * blockDim.x + threadIdx.x) >> 5;
    int lane = threadIdx.x & 31;
    if (warp >= Nn) return;
    int s0 = g_rowstart[warp], s1 = g_rowstart[warp + 1];
    float acc[5] = {0.f, 0.f, 0.f, 0.f, 0.f};
    if (s1 > s0) {
        float m = -INFINITY;
        for (int e = s0 + lane; e < s1; e += 32) m = fmaxf(m, g_logits[e]);
#pragma unroll
        for (int o = 16; o; o >>= 1) m = fmaxf(m, __shfl_xor_sync(0xffffffffu, m, o));
        float den = 0.f;
        for (int e = s0 + lane; e < s1; e += 32) den += expf(g_logits[e] - m);
#pragma unroll
        for (int o = 16; o; o >>= 1) den += __shfl_xor_sync(0xffffffffu, den, o);
        float inv = 1.0f / den;
        for (int e = s0; e < s1; e++) {
            float alpha = expf(g_logits[e] - m) * inv;
            int sidx = src[e];
#pragma unroll
            for (int i = 0; i < 4; i++)
                acc[i] = fmaf(alpha, g_hn[(size_t)sidx * 128 + lane + 32 * i], acc[i]);
            acc[4] = fmaf(alpha * g_aw[e], g_ow[(size_t)e * 32 + lane], acc[4]);
        }
    }
#pragma unroll
    for (int i = 0; i < 4; i++) g_hagg[(size_t)warp * 160 + lane + 32 * i] = acc[i];
    g_hagg[(size_t)warp * 160 + 128 + lane] = acc[4];
}

// ---------------- wout_gemm (FFMA) -------------------------------------------
__global__ __launch_bounds__(256, 2)
void wout_gemm(const float* __restrict__ w, const int* __restrict__ src,
               const int* __restrict__ dst, float* __restrict__ wout, int E) {
    __shared__ float As[32][132];
    __shared__ float Bs[32][132];
    __shared__ float saw[128];
    int tid = threadIdx.x;
    int tx = tid & 15;
    int ty = tid >> 4;
    int row0 = blockIdx.x * 128;

    if (tid < 128) saw[tid] = (row0 + tid < E) ? g_aw[row0 + tid] : 0.f;

    unsigned long long acc[2][4][2][2];
#pragma unroll
    for (int a = 0; a < 2; a++)
#pragma unroll
        for (int b = 0; b < 4; b++)
#pragma unroll
            for (int c = 0; c < 2; c++)
#pragma unroll
                for (int d = 0; d < 2; d++) acc[a][b][c][d] = 0ull;

#pragma unroll
    for (int chunk = 0; chunk < 2; chunk++) {
        const float* Bsrc = chunk == 0 ? g_C2 : g_C1;
        if (chunk) __syncthreads();
#pragma unroll
        for (int i = 0; i < 4; i++) {
            int e = tid + 256 * i;
            int r = e >> 3;
            int kg = e & 7;
            float4 v = make_float4(0.f, 0.f, 0.f, 0.f);
            if (row0 + r < E)
                v = *(const float4*)&w[(size_t)(row0 + r) * 32 + kg * 4];
            float sc = chunk == 0 ? 1.f : saw[r];
            As[kg * 4 + 0][r] = sc * v.x;
            As[kg * 4 + 1][r] = sc * v.y;
            As[kg * 4 + 2][r] = sc * v.z;
            As[kg * 4 + 3][r] = sc * v.w;
        }
#pragma unroll
        for (int i = 0; i < 4; i++) {
            int e = tid + 256 * i;
            int k = e >> 5;
            int cg = e & 31;
            *(float4*)&Bs[k][cg * 4] = *(const float4*)&Bsrc[k * 128 + cg * 4];
        }
        __syncthreads();
#pragma unroll
        for (int k = 0; k < 32; k++) {
            float4 af0 = *(const float4*)&As[k][ty * 4];
            float4 af1 = *(const float4*)&As[k][64 + ty * 4];
            ulonglong2 b0 = *(const ulonglong2*)&Bs[k][tx * 4];
            ulonglong2 b1 = *(const ulonglong2*)&Bs[k][64 + tx * 4];
            float av[2][4] = {{af0.x, af0.y, af0.z, af0.w}, {af1.x, af1.y, af1.z, af1.w}};
#pragma unroll
            for (int mi = 0; mi < 2; mi++)
#pragma unroll
                for (int j = 0; j < 4; j++) {
                    unsigned long long ap = pk2(av[mi][j], av[mi][j]);
                    acc[mi][j][0][0] = ffma2(ap, b0.x, acc[mi][j][0][0]);
                    acc[mi][j][0][1] = ffma2(ap, b0.y, acc[mi][j][0][1]);
                    acc[mi][j][1][0] = ffma2(ap, b1.x, acc[mi][j][1][0]);
                    acc[mi][j][1][1] = ffma2(ap, b1.y, acc[mi][j][1][1]);
                }
        }
    }
    float4 cv0 = *(const float4*)&g_cvec[tx * 4];
    float4 cv1 = *(const float4*)&g_cvec[64 + tx * 4];
#pragma unroll
    for (int mi = 0; mi < 2; mi++)
#pragma unroll
        for (int j = 0; j < 4; j++) {
            int row = row0 + mi * 64 + ty * 4 + j;
            if (row < E) {
                int s = src[row], d = dst[row];
                float4 q1a = *(const float4*)&g_Q1[(size_t)s * 128 + tx * 4];
                float4 q2a = *(const float4*)&g_Q2[(size_t)d * 128 + tx * 4];
                float4 q1b = *(const float4*)&g_Q1[(size_t)s * 128 + 64 + tx * 4];
                float4 q2b = *(const float4*)&g_Q2[(size_t)d * 128 + 64 + tx * 4];
                float z[8];
                upk2(z[0], z[1], acc[mi][j][0][0]);
                upk2(z[2], z[3], acc[mi][j][0][1]);
                upk2(z[4], z[5], acc[mi][j][1][0]);
                upk2(z[6], z[7], acc[mi][j][1][1]);
                float4 o0, o1;
                o0.x = z[0] + q1a.x + q2a.x + cv0.x;
                o0.y = z[1] + q1a.y + q2a.y + cv0.y;
                o0.z = z[2] + q1a.z + q2a.z + cv0.z;
                o0.w = z[3] + q1a.w + q2a.w + cv0.w;
                o1.x = z[4] + q1b.x + q2b.x + cv1.x;
                o1.y = z[5] + q1b.y + q2b.y + cv1.y;
                o1.z = z[6] + q1b.z + q2b.z + cv1.z;
                o1.w = z[7] + q1b.w + q2b.w + cv1.w;
                *(float4*)&wout[(size_t)row * 128 + tx * 4] = o0;
                *(float4*)&wout[(size_t)row * 128 + 64 + tx * 4] = o1;
            }
        }
}

// ---------------- launch ----------------
extern "C" void kernel_launch(void* const* d_in, const int* in_sizes, int n_in,
                              void* d_out, int out_size) {
    const float* h        = (const float*)d_in[0];
    const float* w        = (const float*)d_in[1];
    const int*   src      = (const int*)d_in[2];
    const int*   dst      = (const int*)d_in[3];
    const float* W_en     = (const float*)d_in[4];
    const float* W_attn   = (const float*)d_in[5];
    const float* W_if     = (const float*)d_in[6];
    const float* b_if     = (const float*)d_in[7];
    const float* W_ee     = (const float*)d_in[8];
    const float* W_sf     = (const float*)d_in[9];
    const float* W_conc   = (const float*)d_in[10];
    const float* b_conc   = (const float*)d_in[11];
    const float* bn_gamma = (const float*)d_in[12];
    const float* bn_beta  = (const float*)d_in[13];
    const float* bn_mean  = (const float*)d_in[14];
    const float* bn_var   = (const float*)d_in[15];
    const float* W_ag     = (const float*)d_in[16];

    int Nn = in_sizes[0] / 128;
    int E  = in_sizes[2];

    float* out_hnew = (float*)d_out;
    float* out_wout = out_hnew + (size_t)Nn * 128;
    float* out_sat  = out_wout + (size_t)E * 128;

    float *hn_p, *P1_p, *P2_p, *Q1_p, *Q2_p;
    cudaGetSymbolAddress((void**)&hn_p, g_hn);
    cudaGetSymbolAddress((void**)&P1_p, g_P1);
    cudaGetSymbolAddress((void**)&P2_p, g_P2);
    cudaGetSymbolAddress((void**)&Q1_p, g_Q1);
    cudaGetSymbolAddress((void**)&Q2_p, g_Q2);

    const int G6_SMEM = 2 * BUFSZ * 4;   // 71680 bytes
    cudaFuncSetAttribute(gemm_v6, cudaFuncAttributeMaxDynamicSharedMemorySize, G6_SMEM);
    cudaFuncSetAttribute(gemm_v6_dual, cudaFuncAttributeMaxDynamicSharedMemorySize, G6_SMEM);
    cudaFuncSetAttribute(gemm_conc2, cudaFuncAttributeMaxDynamicSharedMemorySize, G6_SMEM);

    int gbN = (Nn + 127) / 128;
    int gbE = (E + 127) / 128;

    rowstart_kernel<<<(Nn + 256) / 256, 256>>>(dst, E, Nn);
    prep_cmat<<<1, 128>>>(W_if + 256 * 128, W_ag + 256 * 128, W_ee,
                          bn_gamma, bn_beta, bn_mean, bn_var);
    gemm_v6<<<gbN, 256, G6_SMEM>>>(h, W_en, nullptr, hn_p, Nn, 128);
    gemm_v6_dual<<<dim3(gbN, 2), 256, G6_SMEM>>>(hn_p, W_if, W_if + 128 * 128,
                                                 P1_p, P2_p, Nn, 128);
    fuse_gemm_v3<<<gbE, 256>>>(w, src, dst, W_ee, W_sf, b_if, W_attn, out_sat, E);
    segment_kernel<<<(Nn + 7) / 8, 256>>>(src, Nn);
    gemm_conc2<<<gbN, 256, G6_SMEM>>>(W_conc, b_conc, out_hnew, Nn);
    gemm_v6_dual<<<dim3(gbN, 2), 256, G6_SMEM>>>(out_hnew, W_ag, W_ag + 128 * 128,
                                                 Q1_p, Q2_p, Nn, 128);
    wout_gemm<<<gbE, 256>>>(w, src, dst, out_wout, E);
}